// round 16
// baseline (speedup 1.0000x reference)
#include <cuda_runtime.h>
#include <cstdint>
#include <math.h>

#define BATCH 128
#define TT    1024
#define FF    128
#define KK    32
#define NCH   32      // chunks per batch
#define CLEN  32      // measured steps per chunk
#define WARM  8       // warmup steps (Birkhoff contraction ~0.31/step)
#define NBLK  10      // 4-step blocks (WARM+CLEN = 40 iters)
#define NSCAN (BATCH * 2)

// Scratch (device globals: allocation-free per harness rules)
static __device__ unsigned short g_eem_bf[(size_t)BATCH * TT * KK];  // exp(em) bf16, 8MB
static __device__ float         g_expT[KK * KK];  // exp(transition), 4KB
static __device__ long long     g_acc;            // fixed-point (2^-32) accumulator
static __device__ unsigned int  g_done;           // scan block arrival counter

// fast exp on the FMA pipe (rel err ~4e-5 over |x|<~3); avoids the MUFU floor
__device__ __forceinline__ float fast_exp(float x) {
    float t = x * 1.4426950408889634f;
    float n = rintf(t);
    float f = t - n;
    float p = 0.0096853f;
    p = fmaf(p, f, 0.05550411f);
    p = fmaf(p, f, 0.24022651f);
    p = fmaf(p, f, 0.69314718f);
    p = fmaf(p, f, 1.0f);
    return __int_as_float(__float_as_int(p) + (((int)n) << 23));
}

__device__ __forceinline__ uint32_t smem_u32(const void* p) {
    uint32_t a;
    asm("{ .reg .u64 t; cvta.to.shared.u64 t, %1; cvt.u32.u64 %0, t; }" : "=r"(a) : "l"(p));
    return a;
}
__device__ __forceinline__ void cpasync16(uint32_t dst, const void* src) {
    asm volatile("cp.async.cg.shared.global [%0], [%1], 16;" :: "r"(dst), "l"(src));
}
#define CP_COMMIT() asm volatile("cp.async.commit_group;" ::: "memory")
#define CP_WAIT(n)  asm volatile("cp.async.wait_group %0;" :: "n"(n) : "memory")
#define CVT_BF16X2(res, lo, hi) \
    asm("cvt.rn.satfinite.bf16x2.f32 %0, %1, %2;" : "=r"(res) : "f"(hi), "f"(lo))
__device__ __forceinline__ void bf2_to_f2(uint32_t v, float& lo, float& hi) {
    lo = __uint_as_float(v << 16);
    hi = __uint_as_float(v & 0xFFFF0000u);
}

// =====================================================================
// Kernel 1: emission GEMM on mma.sync tf32 + fast exp -> bf16 out.
// BARRIER-FREE mainloop: each warp stages ITS OWN 32 rows via a
// per-warp cp.async 3-buffer ring (per-warp wait_group + syncwarp; the
// 7 per-CTA __syncthreads of the old version collapsed latency hiding).
// =====================================================================
#define XST 36    // Xs row stride (words): A-frag LDS conflict-free (bank 4g+c4)
#define WTS 132   // W^T row stride (words): conflict-free B frags

__global__ __launch_bounds__(128, 3) void emis_mma(const float* __restrict__ x,
                                                   const float* __restrict__ W,
                                                   const float* __restrict__ trans) {
    __shared__ __align__(16) float Xs[4][3][32 * XST];  // [warp][buf] 55.3KB
    __shared__ __align__(16) float Wt[32 * WTS];        // 16.9KB

    const int tid  = threadIdx.x;
    const int lane = tid & 31;
    const int w    = tid >> 5;
    const int g    = lane >> 2;
    const int c4   = lane & 3;
    const int row0 = blockIdx.x * 128;
    const int rw0  = row0 + w * 32;                     // this warp's first row

    // per-warp stage: chunk ch (32 cols) of this warp's 32 rows -> buf
    auto stageX = [&](int ch, int buf) {
        #pragma unroll
        for (int it = 0; it < 8; it++) {
            int idx = it * 32 + lane;
            int r = idx >> 3, q = idx & 7;
            cpasync16(smem_u32(&Xs[w][buf][r * XST + q * 4]),
                      x + (size_t)(rw0 + r) * FF + ch * 32 + q * 4);
        }
        CP_COMMIT();
    };

    stageX(0, 0);      // group 0
    stageX(1, 1);      // group 1

    if (blockIdx.x == 0) {
        if (tid == 0) { g_acc = 0; g_done = 0; }        // replay-safe reset
        #pragma unroll
        for (int i = 0; i < 8; i++)
            g_expT[i * 128 + tid] = expf(trans[i * 128 + tid]);
    }

    // W^T: [n][f] (cooperative; single barrier of the kernel)
    #pragma unroll
    for (int i = 0; i < 32; i++) {
        int idx = i * 128 + tid;
        Wt[(idx & 31) * WTS + (idx >> 5)] = W[idx];
    }
    __syncthreads();

    float d[2][4][4];
    #pragma unroll
    for (int mt = 0; mt < 2; mt++)
        #pragma unroll
        for (int nt = 0; nt < 4; nt++)
            #pragma unroll
            for (int q = 0; q < 4; q++) d[mt][nt][q] = 0.f;

    #pragma unroll
    for (int ch = 0; ch < 4; ch++) {
        const int cur = ch % 3;
        if (ch < 2) stageX(ch + 2, (ch + 2) % 3);       // keep 3 groups in flight
        // wait for group ch (per-warp): allow (#committed - ch - 1) younger pending
        if (ch == 0)      CP_WAIT(2);
        else if (ch == 1) CP_WAIT(2);
        else if (ch == 2) CP_WAIT(1);
        else              CP_WAIT(0);
        __syncwarp();

        uint32_t B0[4][4], B1[4][4];
        #pragma unroll
        for (int ks = 0; ks < 4; ks++)
            #pragma unroll
            for (int nt = 0; nt < 4; nt++) {
                B0[ks][nt] = __float_as_uint(Wt[(nt * 8 + g) * WTS + ch * 32 + ks * 8 + c4]);
                B1[ks][nt] = __float_as_uint(Wt[(nt * 8 + g) * WTS + ch * 32 + ks * 8 + c4 + 4]);
            }

        const float* Xb = Xs[w][cur];
        #pragma unroll
        for (int ks = 0; ks < 4; ks++) {
            uint32_t A[2][4];
            #pragma unroll
            for (int mt = 0; mt < 2; mt++) {
                const int rb = mt * 16;                 // local row within warp tile
                A[mt][0] = __float_as_uint(Xb[(rb + g) * XST + ks * 8 + c4]);
                A[mt][1] = __float_as_uint(Xb[(rb + g + 8) * XST + ks * 8 + c4]);
                A[mt][2] = __float_as_uint(Xb[(rb + g) * XST + ks * 8 + c4 + 4]);
                A[mt][3] = __float_as_uint(Xb[(rb + g + 8) * XST + ks * 8 + c4 + 4]);
            }
            #pragma unroll
            for (int mt = 0; mt < 2; mt++)
                #pragma unroll
                for (int nt = 0; nt < 4; nt++)
                    asm volatile(
                        "mma.sync.aligned.m16n8k8.row.col.f32.tf32.tf32.f32 "
                        "{%0,%1,%2,%3}, {%4,%5,%6,%7}, {%8,%9}, {%0,%1,%2,%3};"
                        : "+f"(d[mt][nt][0]), "+f"(d[mt][nt][1]),
                          "+f"(d[mt][nt][2]), "+f"(d[mt][nt][3])
                        : "r"(A[mt][0]), "r"(A[mt][1]), "r"(A[mt][2]), "r"(A[mt][3]),
                          "r"(B0[ks][nt]), "r"(B1[ks][nt]));
        }
    }

    // Epilogue: exp -> bf16x2 packed stores
    #pragma unroll
    for (int mt = 0; mt < 2; mt++) {
        const int row = rw0 + mt * 16 + g;
        #pragma unroll
        for (int nt = 0; nt < 4; nt++) {
            const int col = nt * 8 + 2 * c4;
            uint32_t p1, p2;
            CVT_BF16X2(p1, fast_exp(d[mt][nt][0]), fast_exp(d[mt][nt][1]));
            CVT_BF16X2(p2, fast_exp(d[mt][nt][2]), fast_exp(d[mt][nt][3]));
            *reinterpret_cast<uint32_t*>(&g_eem_bf[(size_t)row * KK + col]) = p1;
            *reinterpret_cast<uint32_t*>(&g_eem_bf[(size_t)(row + 8) * KK + col]) = p2;
        }
    }
}

// =====================================================================
// Kernel 2: tensor-core scan + fused deterministic reduction.
// (R15 version, unchanged — best measured)
// =====================================================================
#define EST 40    // E4 row stride in bf16 units (80B): conflict-free reads
#define GP  9     // al2 row pad (float2 units)

__global__ __launch_bounds__(32) void scan_mma(const int* __restrict__ mask,
                                               float* __restrict__ out) {
    __shared__ __align__(16) unsigned short E4[2][4][16][EST];  // 10.2KB
    __shared__ __align__(16) float2 al2[2][32][GP];             // [rb][col][g] 4.6KB
    __shared__ __align__(16) int smask[TT];                     // 4KB

    const int b    = blockIdx.x >> 1;
    const int cb   = (blockIdx.x & 1) * 16;
    const int lane = threadIdx.x;
    const int g    = lane >> 2;
    const int c4   = lane & 3;

    const unsigned short* eb = g_eem_bf + (size_t)b * TT * KK;
    const int*            mb = mask + (size_t)b * TT;

    // stage masks — part of group 0
    #pragma unroll
    for (int j = 0; j < 8; j++)
        cpasync16(smem_u32(&smask[(j * 32 + lane) * 4]), mb + (j * 32 + lane) * 4);

    const int sii   = lane >> 3;
    const int sl    = lane & 7;
    const int rhalf = sl >> 2;
    const int ck    = sl & 3;
    auto stage_block = [&](int blk) {
        #pragma unroll
        for (int rr8 = 0; rr8 < 8; rr8++) {
            int rr = rhalf * 8 + rr8;
            int t = 32 * (cb + rr) - WARM + blk * 4 + sii;
            t = max(t, 0);
            cpasync16(smem_u32(&E4[blk & 1][sii][rr][ck * 8]),
                      eb + (size_t)t * KK + ck * 8);
        }
    };

    stage_block(0);
    CP_COMMIT();     // group 0: masks + block 0
    stage_block(1);
    CP_COMMIT();     // group 1

    // B fragments of E = exp(transition) from precomputed table (L2-hot)
    uint32_t B0[4][4], B1[4][4];
    #pragma unroll
    for (int kt = 0; kt < 4; kt++)
        #pragma unroll
        for (int nt = 0; nt < 4; nt++) {
            B0[kt][nt] = __float_as_uint(g_expT[(kt * 8 + c4) * KK + nt * 8 + g]);
            B1[kt][nt] = __float_as_uint(g_expT[(kt * 8 + c4 + 4) * KK + nt * 8 + g]);
        }

    const int ch_g = cb + g;
    const int ch_h = cb + g + 8;
    const bool g0  = (ch_g == 0);
    const int base_g = 32 * ch_g - WARM;
    const int base_h = 32 * ch_h - WARM;

    // alpha init: chunk0 = eem row 0 (t=0), others uniform
    float d[4][4];
    #pragma unroll
    for (int nt = 0; nt < 4; nt++) {
        if (g0) {
            uint32_t v = *reinterpret_cast<const uint32_t*>(eb + nt * 8 + 2 * c4);
            bf2_to_f2(v, d[nt][0], d[nt][1]);
        } else {
            d[nt][0] = 1.f; d[nt][1] = 1.f;
        }
        d[nt][2] = 1.f; d[nt][3] = 1.f;
    }
    #pragma unroll
    for (int nt = 0; nt < 4; nt++) {
        al2[0][nt * 8 + 2 * c4][g]     = make_float2(d[nt][0], d[nt][2]);
        al2[0][nt * 8 + 2 * c4 + 1][g] = make_float2(d[nt][1], d[nt][3]);
    }

    CP_WAIT(1);
    __syncwarp();

    int oe_g = 0, oe_h = 0, oes_g = 0, oes_h = 0;
    float snl_g = 0.f, snl_h = 0.f;
    const float z = 0.f;

    #pragma unroll 1
    for (int blk = 0; blk < NBLK; blk++) {
        const int buf = blk & 1;
        #pragma unroll
        for (int ii = 0; ii < 4; ii++) {
            const int i  = blk * 4 + ii;
            const int rb = i & 1, wb = rb ^ 1;

            // A fragments: 8 x LDS.64 (paired rows g / g+8)
            uint32_t A0[4], A1[4], A2[4], A3[4];
            #pragma unroll
            for (int kt = 0; kt < 4; kt++) {
                float2 v0 = al2[rb][kt * 8 + c4][g];
                float2 v1 = al2[rb][kt * 8 + c4 + 4][g];
                A0[kt] = __float_as_uint(v0.x);
                A1[kt] = __float_as_uint(v0.y);
                A2[kt] = __float_as_uint(v1.x);
                A3[kt] = __float_as_uint(v1.y);
            }

            // 16 MMAs: two 2-deep chains per ntile + FADD merge
            float dA[4][4], dB[4][4];
            #pragma unroll
            for (int nt = 0; nt < 4; nt++) {
                asm volatile(
                    "mma.sync.aligned.m16n8k8.row.col.f32.tf32.tf32.f32 "
                    "{%0,%1,%2,%3}, {%4,%5,%6,%7}, {%8,%9}, {%10,%11,%12,%13};"
                    : "=f"(dA[nt][0]), "=f"(dA[nt][1]), "=f"(dA[nt][2]), "=f"(dA[nt][3])
                    : "r"(A0[0]), "r"(A1[0]), "r"(A2[0]), "r"(A3[0]),
                      "r"(B0[0][nt]), "r"(B1[0][nt]), "f"(z), "f"(z), "f"(z), "f"(z));
                asm volatile(
                    "mma.sync.aligned.m16n8k8.row.col.f32.tf32.tf32.f32 "
                    "{%0,%1,%2,%3}, {%4,%5,%6,%7}, {%8,%9}, {%0,%1,%2,%3};"
                    : "+f"(dA[nt][0]), "+f"(dA[nt][1]), "+f"(dA[nt][2]), "+f"(dA[nt][3])
                    : "r"(A0[1]), "r"(A1[1]), "r"(A2[1]), "r"(A3[1]),
                      "r"(B0[1][nt]), "r"(B1[1][nt]));
                asm volatile(
                    "mma.sync.aligned.m16n8k8.row.col.f32.tf32.tf32.f32 "
                    "{%0,%1,%2,%3}, {%4,%5,%6,%7}, {%8,%9}, {%10,%11,%12,%13};"
                    : "=f"(dB[nt][0]), "=f"(dB[nt][1]), "=f"(dB[nt][2]), "=f"(dB[nt][3])
                    : "r"(A0[2]), "r"(A1[2]), "r"(A2[2]), "r"(A3[2]),
                      "r"(B0[2][nt]), "r"(B1[2][nt]), "f"(z), "f"(z), "f"(z), "f"(z));
                asm volatile(
                    "mma.sync.aligned.m16n8k8.row.col.f32.tf32.tf32.f32 "
                    "{%0,%1,%2,%3}, {%4,%5,%6,%7}, {%8,%9}, {%0,%1,%2,%3};"
                    : "+f"(dB[nt][0]), "+f"(dB[nt][1]), "+f"(dB[nt][2]), "+f"(dB[nt][3])
                    : "r"(A0[3]), "r"(A1[3]), "r"(A2[3]), "r"(A3[3]),
                      "r"(B0[3][nt]), "r"(B1[3][nt]));
            }

            const int tg = base_g + i, th = base_h + i;
            const int mg = (tg >= 1) ? smask[tg] : 0;
            const int mh = (th >= 1) ? smask[th] : 0;

            #pragma unroll
            for (int nt = 0; nt < 4; nt++) {
                uint32_t vg = *reinterpret_cast<const uint32_t*>(&E4[buf][ii][g][nt * 8 + 2 * c4]);
                uint32_t vh = *reinterpret_cast<const uint32_t*>(&E4[buf][ii][g + 8][nt * 8 + 2 * c4]);
                float egx, egy, ehx, ehy;
                bf2_to_f2(vg, egx, egy);
                bf2_to_f2(vh, ehx, ehy);
                float n0 = (dA[nt][0] + dB[nt][0]) * egx;
                float n1 = (dA[nt][1] + dB[nt][1]) * egy;
                float n2 = (dA[nt][2] + dB[nt][2]) * ehx;
                float n3 = (dA[nt][3] + dB[nt][3]) * ehy;
                d[nt][0] = mg ? n0 : d[nt][0];
                d[nt][1] = mg ? n1 : d[nt][1];
                d[nt][2] = mh ? n2 : d[nt][2];
                d[nt][3] = mh ? n3 : d[nt][3];
            }

            if ((i & 7) == 7) {
                float mxg = d[0][0], mxh = d[0][2];
                #pragma unroll
                for (int nt = 0; nt < 4; nt++) {
                    mxg = fmaxf(mxg, fmaxf(d[nt][0], d[nt][1]));
                    mxh = fmaxf(mxh, fmaxf(d[nt][2], d[nt][3]));
                }
                mxg = fmaxf(mxg, __shfl_xor_sync(0xffffffffu, mxg, 1));
                mxg = fmaxf(mxg, __shfl_xor_sync(0xffffffffu, mxg, 2));
                mxh = fmaxf(mxh, __shfl_xor_sync(0xffffffffu, mxh, 1));
                mxh = fmaxf(mxh, __shfl_xor_sync(0xffffffffu, mxh, 2));
                int eig = (__float_as_int(mxg) >> 23) & 255;
                int eih = (__float_as_int(mxh) >> 23) & 255;
                oe_g += eig - 127;
                oe_h += eih - 127;
                float sg_ = __int_as_float((254 - eig) << 23);
                float sh_ = __int_as_float((254 - eih) << 23);
                #pragma unroll
                for (int nt = 0; nt < 4; nt++) {
                    d[nt][0] *= sg_; d[nt][1] *= sg_;
                    d[nt][2] *= sh_; d[nt][3] *= sh_;
                }
            }

            if (i == WARM - 1) {      // snapshot after warmup (post-renorm)
                float sg_ = 0.f, sh_ = 0.f;
                #pragma unroll
                for (int nt = 0; nt < 4; nt++) {
                    sg_ += d[nt][0] + d[nt][1];
                    sh_ += d[nt][2] + d[nt][3];
                }
                sg_ += __shfl_xor_sync(0xffffffffu, sg_, 1);
                sg_ += __shfl_xor_sync(0xffffffffu, sg_, 2);
                sh_ += __shfl_xor_sync(0xffffffffu, sh_, 1);
                sh_ += __shfl_xor_sync(0xffffffffu, sh_, 2);
                snl_g = g0 ? 0.f : logf(sg_);
                oes_g = g0 ? 0 : oe_g;
                snl_h = logf(sh_);
                oes_h = oe_h;
            }

            #pragma unroll
            for (int nt = 0; nt < 4; nt++) {
                al2[wb][nt * 8 + 2 * c4][g]     = make_float2(d[nt][0], d[nt][2]);
                al2[wb][nt * 8 + 2 * c4 + 1][g] = make_float2(d[nt][1], d[nt][3]);
            }
            __syncwarp();
        }

        if (blk < NBLK - 2) { stage_block(blk + 2); CP_COMMIT(); CP_WAIT(1); }
        else                { CP_WAIT(0); }
        __syncwarp();
    }

    float sg_ = 0.f, sh_ = 0.f;
    #pragma unroll
    for (int nt = 0; nt < 4; nt++) {
        sg_ += d[nt][0] + d[nt][1];
        sh_ += d[nt][2] + d[nt][3];
    }
    sg_ += __shfl_xor_sync(0xffffffffu, sg_, 1);
    sg_ += __shfl_xor_sync(0xffffffffu, sg_, 2);
    sh_ += __shfl_xor_sync(0xffffffffu, sh_, 1);
    sh_ += __shfl_xor_sync(0xffffffffu, sh_, 2);

    const float LN2 = 0.69314718055994531f;
    float Dg = (float)(oe_g - oes_g) * LN2 + logf(sg_) - snl_g;
    float Dh = (float)(oe_h - oes_h) * LN2 + logf(sh_) - snl_h;

    // fused deterministic reduction (fixed-point 2^-32 integer atomics)
    float v = (c4 == 0) ? (Dg + Dh) : 0.f;
    #pragma unroll
    for (int off = 16; off > 0; off >>= 1)
        v += __shfl_xor_sync(0xffffffffu, v, off);

    if (lane == 0) {
        long long q = llrint((double)v * 4294967296.0);
        atomicAdd((unsigned long long*)&g_acc, (unsigned long long)q);
        __threadfence();
        unsigned int done = atomicInc(&g_done, NSCAN - 1);
        if (done == NSCAN - 1) {
            long long tot = (long long)atomicAdd((unsigned long long*)&g_acc, 0ULL);
            out[0] = (float)((double)tot * (1.0 / 4294967296.0));
        }
    }
}

extern "C" void kernel_launch(void* const* d_in, const int* in_sizes, int n_in,
                              void* d_out, int out_size) {
    const float* x     = (const float*)d_in[0];
    const int*   mask  = (const int*)d_in[1];
    const float* W     = (const float*)d_in[2];
    const float* trans = (const float*)d_in[3];

    emis_mma<<<(BATCH * TT) / 128, 128>>>(x, W, trans);
    scan_mma<<<NSCAN, 32>>>(mask, (float*)d_out);
}

// round 17
// speedup vs baseline: 1.0736x; 1.0736x over previous
#include <cuda_runtime.h>
#include <cstdint>
#include <math.h>

#define BATCH 128
#define TT    1024
#define FF    128
#define KK    32
#define NCH   64      // chunks per batch
#define CLEN  16      // measured steps per chunk
#define WARM  8       // warmup steps (Birkhoff contraction ~0.31/step)
#define NBLK  6       // 4-step blocks (WARM+CLEN = 24 iters)
#define NSCAN (BATCH * 4)

// Scratch (device globals: allocation-free per harness rules)
static __device__ unsigned short g_eem_bf[(size_t)BATCH * TT * KK];  // exp(em) bf16, 8MB
static __device__ float         g_expT[KK * KK];  // exp(transition), 4KB
static __device__ long long     g_acc;            // fixed-point (2^-32) accumulator
static __device__ unsigned int  g_done;           // scan block arrival counter

// fast exp on the FMA pipe (rel err ~4e-5 over |x|<~3); avoids the MUFU floor
__device__ __forceinline__ float fast_exp(float x) {
    float t = x * 1.4426950408889634f;
    float n = rintf(t);
    float f = t - n;
    float p = 0.0096853f;
    p = fmaf(p, f, 0.05550411f);
    p = fmaf(p, f, 0.24022651f);
    p = fmaf(p, f, 0.69314718f);
    p = fmaf(p, f, 1.0f);
    return __int_as_float(__float_as_int(p) + (((int)n) << 23));
}

__device__ __forceinline__ uint32_t smem_u32(const void* p) {
    uint32_t a;
    asm("{ .reg .u64 t; cvta.to.shared.u64 t, %1; cvt.u32.u64 %0, t; }" : "=r"(a) : "l"(p));
    return a;
}
__device__ __forceinline__ void cpasync16(uint32_t dst, const void* src) {
    asm volatile("cp.async.cg.shared.global [%0], [%1], 16;" :: "r"(dst), "l"(src));
}
#define CP_COMMIT() asm volatile("cp.async.commit_group;" ::: "memory")
#define CP_WAIT(n)  asm volatile("cp.async.wait_group %0;" :: "n"(n) : "memory")
#define CVT_BF16X2(res, lo, hi) \
    asm("cvt.rn.satfinite.bf16x2.f32 %0, %1, %2;" : "=r"(res) : "f"(hi), "f"(lo))
__device__ __forceinline__ void bf2_to_f2(uint32_t v, float& lo, float& hi) {
    lo = __uint_as_float(v << 16);
    hi = __uint_as_float(v & 0xFFFF0000u);
}

// =====================================================================
// Kernel 1: emission GEMM on mma.sync tf32 + fast exp -> bf16 out.
// (R15 proven version: cp.async double-buffered, W^T smem)
// =====================================================================
#define XST 36    // Xs row stride (words): A-frag LDS conflict-free
#define WTS 132   // W^T row stride (words): conflict-free B frags

__global__ __launch_bounds__(128, 4) void emis_mma(const float* __restrict__ x,
                                                   const float* __restrict__ W,
                                                   const float* __restrict__ trans) {
    __shared__ __align__(16) float Xs[2][128 * XST];   // 36.9KB
    __shared__ __align__(16) float Wt[32 * WTS];       // 16.9KB

    const int tid  = threadIdx.x;
    const int lane = tid & 31;
    const int w    = tid >> 5;
    const int g    = lane >> 2;
    const int c4   = lane & 3;
    const int row0 = blockIdx.x * 128;

    if (blockIdx.x == 0) {
        if (tid == 0) { g_acc = 0; g_done = 0; }       // replay-safe reset
        #pragma unroll
        for (int i = 0; i < 8; i++)
            g_expT[i * 128 + tid] = expf(trans[i * 128 + tid]);
    }

    auto stageX = [&](int ch, int buf) {
        #pragma unroll
        for (int it = 0; it < 8; it++) {
            int idx = it * 128 + tid;
            int r = idx >> 3, q = idx & 7;
            cpasync16(smem_u32(&Xs[buf][r * XST + q * 4]),
                      x + (size_t)(row0 + r) * FF + ch * 32 + q * 4);
        }
        CP_COMMIT();
    };

    stageX(0, 0);

    // W^T: [n][f]
    #pragma unroll
    for (int i = 0; i < 32; i++) {
        int idx = i * 128 + tid;
        Wt[(idx & 31) * WTS + (idx >> 5)] = W[idx];
    }

    float d[2][4][4];
    #pragma unroll
    for (int mt = 0; mt < 2; mt++)
        #pragma unroll
        for (int nt = 0; nt < 4; nt++)
            #pragma unroll
            for (int q = 0; q < 4; q++) d[mt][nt][q] = 0.f;

    #pragma unroll
    for (int ch = 0; ch < 4; ch++) {
        const int cur = ch & 1;
        if (ch < 3) stageX(ch + 1, cur ^ 1);
        if (ch < 3) { CP_WAIT(1); } else { CP_WAIT(0); }
        __syncthreads();

        uint32_t B0[4][4], B1[4][4];
        #pragma unroll
        for (int ks = 0; ks < 4; ks++)
            #pragma unroll
            for (int nt = 0; nt < 4; nt++) {
                B0[ks][nt] = __float_as_uint(Wt[(nt * 8 + g) * WTS + ch * 32 + ks * 8 + c4]);
                B1[ks][nt] = __float_as_uint(Wt[(nt * 8 + g) * WTS + ch * 32 + ks * 8 + c4 + 4]);
            }

        #pragma unroll
        for (int ks = 0; ks < 4; ks++) {
            uint32_t A[2][4];
            #pragma unroll
            for (int mt = 0; mt < 2; mt++) {
                const int rb = w * 32 + mt * 16;
                A[mt][0] = __float_as_uint(Xs[cur][(rb + g) * XST + ks * 8 + c4]);
                A[mt][1] = __float_as_uint(Xs[cur][(rb + g + 8) * XST + ks * 8 + c4]);
                A[mt][2] = __float_as_uint(Xs[cur][(rb + g) * XST + ks * 8 + c4 + 4]);
                A[mt][3] = __float_as_uint(Xs[cur][(rb + g + 8) * XST + ks * 8 + c4 + 4]);
            }
            #pragma unroll
            for (int mt = 0; mt < 2; mt++)
                #pragma unroll
                for (int nt = 0; nt < 4; nt++)
                    asm volatile(
                        "mma.sync.aligned.m16n8k8.row.col.f32.tf32.tf32.f32 "
                        "{%0,%1,%2,%3}, {%4,%5,%6,%7}, {%8,%9}, {%0,%1,%2,%3};"
                        : "+f"(d[mt][nt][0]), "+f"(d[mt][nt][1]),
                          "+f"(d[mt][nt][2]), "+f"(d[mt][nt][3])
                        : "r"(A[mt][0]), "r"(A[mt][1]), "r"(A[mt][2]), "r"(A[mt][3]),
                          "r"(B0[ks][nt]), "r"(B1[ks][nt]));
        }
        if (ch < 3) __syncthreads();
    }

    // Epilogue: exp -> bf16x2 packed stores
    #pragma unroll
    for (int mt = 0; mt < 2; mt++) {
        const int row = row0 + w * 32 + mt * 16 + g;
        #pragma unroll
        for (int nt = 0; nt < 4; nt++) {
            const int col = nt * 8 + 2 * c4;
            uint32_t p1, p2;
            CVT_BF16X2(p1, fast_exp(d[mt][nt][0]), fast_exp(d[mt][nt][1]));
            CVT_BF16X2(p2, fast_exp(d[mt][nt][2]), fast_exp(d[mt][nt][3]));
            *reinterpret_cast<uint32_t*>(&g_eem_bf[(size_t)row * KK + col]) = p1;
            *reinterpret_cast<uint32_t*>(&g_eem_bf[(size_t)(row + 8) * KK + col]) = p2;
        }
    }
}

// =====================================================================
// Kernel 2: tensor-core scan + fused deterministic reduction.
// NCH=64 / CLEN=16 / WARM=8 -> 24-iter chain (was 40); 512 blocks
// (still <= 592 SMSPs). Per-block startup is now cheap (g_expT table,
// cp.async masks) so shorter chains finally win.
// Chunk c: warmup t in [16c-8, 16c), measured [16c, 16c+16);
// chunk 0: warmup masked off, measured [1, 16).
// =====================================================================
#define EST 40    // E4 row stride in bf16 units (80B): conflict-free reads
#define GP  9     // al2 row pad (float2 units)

__global__ __launch_bounds__(32) void scan_mma(const int* __restrict__ mask,
                                               float* __restrict__ out) {
    __shared__ __align__(16) unsigned short E4[2][4][16][EST];  // 10.2KB
    __shared__ __align__(16) float2 al2[2][32][GP];             // [rb][col][g] 4.6KB
    __shared__ __align__(16) int smask[TT];                     // 4KB

    const int b    = blockIdx.x >> 2;
    const int cb   = (blockIdx.x & 3) * 16;
    const int lane = threadIdx.x;
    const int g    = lane >> 2;
    const int c4   = lane & 3;

    const unsigned short* eb = g_eem_bf + (size_t)b * TT * KK;
    const int*            mb = mask + (size_t)b * TT;

    // stage masks — part of group 0
    #pragma unroll
    for (int j = 0; j < 8; j++)
        cpasync16(smem_u32(&smask[(j * 32 + lane) * 4]), mb + (j * 32 + lane) * 4);

    const int sii   = lane >> 3;
    const int sl    = lane & 7;
    const int rhalf = sl >> 2;
    const int ck    = sl & 3;
    auto stage_block = [&](int blk) {
        #pragma unroll
        for (int rr8 = 0; rr8 < 8; rr8++) {
            int rr = rhalf * 8 + rr8;
            int t = 16 * (cb + rr) - WARM + blk * 4 + sii;
            t = max(t, 0);
            cpasync16(smem_u32(&E4[blk & 1][sii][rr][ck * 8]),
                      eb + (size_t)t * KK + ck * 8);
        }
    };

    stage_block(0);
    CP_COMMIT();     // group 0: masks + block 0
    stage_block(1);
    CP_COMMIT();     // group 1

    // B fragments of E = exp(transition) from precomputed table (L2-hot)
    uint32_t B0[4][4], B1[4][4];
    #pragma unroll
    for (int kt = 0; kt < 4; kt++)
        #pragma unroll
        for (int nt = 0; nt < 4; nt++) {
            B0[kt][nt] = __float_as_uint(g_expT[(kt * 8 + c4) * KK + nt * 8 + g]);
            B1[kt][nt] = __float_as_uint(g_expT[(kt * 8 + c4 + 4) * KK + nt * 8 + g]);
        }

    const int ch_g = cb + g;
    const int ch_h = cb + g + 8;
    const bool g0  = (ch_g == 0);
    const int base_g = 16 * ch_g - WARM;
    const int base_h = 16 * ch_h - WARM;

    // alpha init: chunk0 = eem row 0 (t=0), others uniform
    float d[4][4];
    #pragma unroll
    for (int nt = 0; nt < 4; nt++) {
        if (g0) {
            uint32_t v = *reinterpret_cast<const uint32_t*>(eb + nt * 8 + 2 * c4);
            bf2_to_f2(v, d[nt][0], d[nt][1]);
        } else {
            d[nt][0] = 1.f; d[nt][1] = 1.f;
        }
        d[nt][2] = 1.f; d[nt][3] = 1.f;
    }
    #pragma unroll
    for (int nt = 0; nt < 4; nt++) {
        al2[0][nt * 8 + 2 * c4][g]     = make_float2(d[nt][0], d[nt][2]);
        al2[0][nt * 8 + 2 * c4 + 1][g] = make_float2(d[nt][1], d[nt][3]);
    }

    CP_WAIT(1);
    __syncwarp();

    int oe_g = 0, oe_h = 0, oes_g = 0, oes_h = 0;
    float snl_g = 0.f, snl_h = 0.f;
    const float z = 0.f;

    #pragma unroll 1
    for (int blk = 0; blk < NBLK; blk++) {
        const int buf = blk & 1;
        #pragma unroll
        for (int ii = 0; ii < 4; ii++) {
            const int i  = blk * 4 + ii;
            const int rb = i & 1, wb = rb ^ 1;

            // A fragments: 8 x LDS.64 (paired rows g / g+8)
            uint32_t A0[4], A1[4], A2[4], A3[4];
            #pragma unroll
            for (int kt = 0; kt < 4; kt++) {
                float2 v0 = al2[rb][kt * 8 + c4][g];
                float2 v1 = al2[rb][kt * 8 + c4 + 4][g];
                A0[kt] = __float_as_uint(v0.x);
                A1[kt] = __float_as_uint(v0.y);
                A2[kt] = __float_as_uint(v1.x);
                A3[kt] = __float_as_uint(v1.y);
            }

            // 16 MMAs: two 2-deep chains per ntile + FADD merge
            float dA[4][4], dB[4][4];
            #pragma unroll
            for (int nt = 0; nt < 4; nt++) {
                asm volatile(
                    "mma.sync.aligned.m16n8k8.row.col.f32.tf32.tf32.f32 "
                    "{%0,%1,%2,%3}, {%4,%5,%6,%7}, {%8,%9}, {%10,%11,%12,%13};"
                    : "=f"(dA[nt][0]), "=f"(dA[nt][1]), "=f"(dA[nt][2]), "=f"(dA[nt][3])
                    : "r"(A0[0]), "r"(A1[0]), "r"(A2[0]), "r"(A3[0]),
                      "r"(B0[0][nt]), "r"(B1[0][nt]), "f"(z), "f"(z), "f"(z), "f"(z));
                asm volatile(
                    "mma.sync.aligned.m16n8k8.row.col.f32.tf32.tf32.f32 "
                    "{%0,%1,%2,%3}, {%4,%5,%6,%7}, {%8,%9}, {%0,%1,%2,%3};"
                    : "+f"(dA[nt][0]), "+f"(dA[nt][1]), "+f"(dA[nt][2]), "+f"(dA[nt][3])
                    : "r"(A0[1]), "r"(A1[1]), "r"(A2[1]), "r"(A3[1]),
                      "r"(B0[1][nt]), "r"(B1[1][nt]));
                asm volatile(
                    "mma.sync.aligned.m16n8k8.row.col.f32.tf32.tf32.f32 "
                    "{%0,%1,%2,%3}, {%4,%5,%6,%7}, {%8,%9}, {%10,%11,%12,%13};"
                    : "=f"(dB[nt][0]), "=f"(dB[nt][1]), "=f"(dB[nt][2]), "=f"(dB[nt][3])
                    : "r"(A0[2]), "r"(A1[2]), "r"(A2[2]), "r"(A3[2]),
                      "r"(B0[2][nt]), "r"(B1[2][nt]), "f"(z), "f"(z), "f"(z), "f"(z));
                asm volatile(
                    "mma.sync.aligned.m16n8k8.row.col.f32.tf32.tf32.f32 "
                    "{%0,%1,%2,%3}, {%4,%5,%6,%7}, {%8,%9}, {%0,%1,%2,%3};"
                    : "+f"(dB[nt][0]), "+f"(dB[nt][1]), "+f"(dB[nt][2]), "+f"(dB[nt][3])
                    : "r"(A0[3]), "r"(A1[3]), "r"(A2[3]), "r"(A3[3]),
                      "r"(B0[3][nt]), "r"(B1[3][nt]));
            }

            const int tg = base_g + i, th = base_h + i;
            const int mg = (tg >= 1) ? smask[tg] : 0;
            const int mh = (th >= 1) ? smask[th] : 0;

            #pragma unroll
            for (int nt = 0; nt < 4; nt++) {
                uint32_t vg = *reinterpret_cast<const uint32_t*>(&E4[buf][ii][g][nt * 8 + 2 * c4]);
                uint32_t vh = *reinterpret_cast<const uint32_t*>(&E4[buf][ii][g + 8][nt * 8 + 2 * c4]);
                float egx, egy, ehx, ehy;
                bf2_to_f2(vg, egx, egy);
                bf2_to_f2(vh, ehx, ehy);
                float n0 = (dA[nt][0] + dB[nt][0]) * egx;
                float n1 = (dA[nt][1] + dB[nt][1]) * egy;
                float n2 = (dA[nt][2] + dB[nt][2]) * ehx;
                float n3 = (dA[nt][3] + dB[nt][3]) * ehy;
                d[nt][0] = mg ? n0 : d[nt][0];
                d[nt][1] = mg ? n1 : d[nt][1];
                d[nt][2] = mh ? n2 : d[nt][2];
                d[nt][3] = mh ? n3 : d[nt][3];
            }

            if ((i & 7) == 7) {
                float mxg = d[0][0], mxh = d[0][2];
                #pragma unroll
                for (int nt = 0; nt < 4; nt++) {
                    mxg = fmaxf(mxg, fmaxf(d[nt][0], d[nt][1]));
                    mxh = fmaxf(mxh, fmaxf(d[nt][2], d[nt][3]));
                }
                mxg = fmaxf(mxg, __shfl_xor_sync(0xffffffffu, mxg, 1));
                mxg = fmaxf(mxg, __shfl_xor_sync(0xffffffffu, mxg, 2));
                mxh = fmaxf(mxh, __shfl_xor_sync(0xffffffffu, mxh, 1));
                mxh = fmaxf(mxh, __shfl_xor_sync(0xffffffffu, mxh, 2));
                int eig = (__float_as_int(mxg) >> 23) & 255;
                int eih = (__float_as_int(mxh) >> 23) & 255;
                oe_g += eig - 127;
                oe_h += eih - 127;
                float sg_ = __int_as_float((254 - eig) << 23);
                float sh_ = __int_as_float((254 - eih) << 23);
                #pragma unroll
                for (int nt = 0; nt < 4; nt++) {
                    d[nt][0] *= sg_; d[nt][1] *= sg_;
                    d[nt][2] *= sh_; d[nt][3] *= sh_;
                }
            }

            if (i == WARM - 1) {      // snapshot after warmup (post-renorm)
                float sg_ = 0.f, sh_ = 0.f;
                #pragma unroll
                for (int nt = 0; nt < 4; nt++) {
                    sg_ += d[nt][0] + d[nt][1];
                    sh_ += d[nt][2] + d[nt][3];
                }
                sg_ += __shfl_xor_sync(0xffffffffu, sg_, 1);
                sg_ += __shfl_xor_sync(0xffffffffu, sg_, 2);
                sh_ += __shfl_xor_sync(0xffffffffu, sh_, 1);
                sh_ += __shfl_xor_sync(0xffffffffu, sh_, 2);
                snl_g = g0 ? 0.f : logf(sg_);
                oes_g = g0 ? 0 : oe_g;
                snl_h = logf(sh_);
                oes_h = oe_h;
            }

            #pragma unroll
            for (int nt = 0; nt < 4; nt++) {
                al2[wb][nt * 8 + 2 * c4][g]     = make_float2(d[nt][0], d[nt][2]);
                al2[wb][nt * 8 + 2 * c4 + 1][g] = make_float2(d[nt][1], d[nt][3]);
            }
            __syncwarp();
        }

        if (blk < NBLK - 2) { stage_block(blk + 2); CP_COMMIT(); CP_WAIT(1); }
        else                { CP_WAIT(0); }
        __syncwarp();
    }

    float sg_ = 0.f, sh_ = 0.f;
    #pragma unroll
    for (int nt = 0; nt < 4; nt++) {
        sg_ += d[nt][0] + d[nt][1];
        sh_ += d[nt][2] + d[nt][3];
    }
    sg_ += __shfl_xor_sync(0xffffffffu, sg_, 1);
    sg_ += __shfl_xor_sync(0xffffffffu, sg_, 2);
    sh_ += __shfl_xor_sync(0xffffffffu, sh_, 1);
    sh_ += __shfl_xor_sync(0xffffffffu, sh_, 2);

    const float LN2 = 0.69314718055994531f;
    float Dg = (float)(oe_g - oes_g) * LN2 + logf(sg_) - snl_g;
    float Dh = (float)(oe_h - oes_h) * LN2 + logf(sh_) - snl_h;

    // fused deterministic reduction (fixed-point 2^-32 integer atomics)
    float v = (c4 == 0) ? (Dg + Dh) : 0.f;
    #pragma unroll
    for (int off = 16; off > 0; off >>= 1)
        v += __shfl_xor_sync(0xffffffffu, v, off);

    if (lane == 0) {
        long long q = llrint((double)v * 4294967296.0);
        atomicAdd((unsigned long long*)&g_acc, (unsigned long long)q);
        __threadfence();
        unsigned int done = atomicInc(&g_done, NSCAN - 1);
        if (done == NSCAN - 1) {
            long long tot = (long long)atomicAdd((unsigned long long*)&g_acc, 0ULL);
            out[0] = (float)((double)tot * (1.0 / 4294967296.0));
        }
    }
}

extern "C" void kernel_launch(void* const* d_in, const int* in_sizes, int n_in,
                              void* d_out, int out_size) {
    const float* x     = (const float*)d_in[0];
    const int*   mask  = (const int*)d_in[1];
    const float* W     = (const float*)d_in[2];
    const float* trans = (const float*)d_in[3];

    emis_mma<<<(BATCH * TT) / 128, 128>>>(x, W, trans);
    scan_mma<<<NSCAN, 32>>>(mask, (float*)d_out);
}